// round 14
// baseline (speedup 1.0000x reference)
#include <cuda_runtime.h>
#include <cuda_bf16.h>
#include <stdint.h>
#include <math.h>

// Problem constants (fixed by setup_inputs)
#define S     2048
#define HID   2048
#define NHEAD 16
#define HDIM  128
#define HDTOT 2048

typedef __nv_bfloat16 bf16;

// ---------------- static device scratch ----------------
__device__ bf16  g_Xh [S * HID],     g_Xl [S * HID];
__device__ bf16  g_qwh[HDTOT * HID], g_qwl[HDTOT * HID];
__device__ bf16  g_kwh[HDTOT * HID], g_kwl[HDTOT * HID];
__device__ bf16  g_vwh[HDTOT * HID], g_vwl[HDTOT * HID];
__device__ bf16  g_owh[HID * HDTOT], g_owl[HID * HDTOT];
__device__ bf16  g_qh [S * HDTOT], g_ql [S * HDTOT];
__device__ bf16  g_kh [S * HDTOT], g_kl [S * HDTOT];
__device__ bf16  g_vh [S * HDTOT], g_vl [S * HDTOT];
__device__ bf16  g_vth[HDTOT * S], g_vtl[HDTOT * S];   // V transposed (H*D, S)
__device__ bf16  g_ath[S * HDTOT], g_atl[S * HDTOT];
__device__ float g_scores[(size_t)NHEAD * S * S];      // holds E = exp(scaled scores)
// per-row softmax stats (NHEAD*S rows)
__device__ float  g_EmaxB[NHEAD * S], g_LB[NHEAD * S];
__device__ float  g_EmaxC[NHEAD * S], g_LC[NHEAD * S];
__device__ float2 g_K12[NHEAD * S];

// ---------------- PTX helpers (base compute_103 features only) ----------------
__device__ __forceinline__ uint32_t smem_u32(const void* p) {
    uint32_t a;
    asm("{ .reg .u64 t; cvta.to.shared.u64 t, %1; cvt.u32.u64 %0, t; }" : "=r"(a) : "l"(p));
    return a;
}
__device__ __forceinline__ void cp16(uint32_t s, const void* g) {
    asm volatile("cp.async.cg.shared.global [%0], [%1], 16;" :: "r"(s), "l"(g));
}
#define CP_COMMIT() asm volatile("cp.async.commit_group;" ::: "memory")

#define LDSM4(r, addr) \
    asm volatile("ldmatrix.sync.aligned.m8n8.x4.shared.b16 {%0,%1,%2,%3}, [%4];" \
        : "=r"((r)[0]), "=r"((r)[1]), "=r"((r)[2]), "=r"((r)[3]) : "r"(addr))

#define MMA(cc, aa, b0, b1) \
    asm volatile("mma.sync.aligned.m16n8k16.row.col.f32.bf16.bf16.f32 " \
        "{%0,%1,%2,%3}, {%4,%5,%6,%7}, {%8,%9}, {%0,%1,%2,%3};" \
        : "+f"((cc)[0]), "+f"((cc)[1]), "+f"((cc)[2]), "+f"((cc)[3]) \
        : "r"((aa)[0]), "r"((aa)[1]), "r"((aa)[2]), "r"((aa)[3]), "r"(b0), "r"(b1))

// ---------------- merged split kernel: 5 fp32 tensors -> bf16 hi/lo ----------------
struct SplitArgs {
    const float* s[5];
    bf16* h[5];
    bf16* l[5];
};

__global__ __launch_bounds__(256)
void split5(SplitArgs a) {
    const int set = blockIdx.y;
    const int i = blockIdx.x * 256 + threadIdx.x;
    float4 v = ((const float4*)a.s[set])[i];
    bf16 h0 = __float2bfloat16_rn(v.x), h1 = __float2bfloat16_rn(v.y);
    bf16 h2 = __float2bfloat16_rn(v.z), h3 = __float2bfloat16_rn(v.w);
    bf16 l0 = __float2bfloat16_rn(v.x - __bfloat162float(h0));
    bf16 l1 = __float2bfloat16_rn(v.y - __bfloat162float(h1));
    bf16 l2 = __float2bfloat16_rn(v.z - __bfloat162float(h2));
    bf16 l3 = __float2bfloat16_rn(v.w - __bfloat162float(h3));
    ((__nv_bfloat162*)a.h[set])[2 * i]     = __halves2bfloat162(h0, h1);
    ((__nv_bfloat162*)a.h[set])[2 * i + 1] = __halves2bfloat162(h2, h3);
    ((__nv_bfloat162*)a.l[set])[2 * i]     = __halves2bfloat162(l0, l1);
    ((__nv_bfloat162*)a.l[set])[2 * i + 1] = __halves2bfloat162(l2, l3);
}

// ---------------- bf16 transpose ----------------
__global__ __launch_bounds__(256)
void transpose_b16(const bf16* __restrict__ sh, const bf16* __restrict__ sl,
                   bf16* __restrict__ th, bf16* __restrict__ tl) {
    __shared__ bf16 t0[32][34];
    __shared__ bf16 t1[32][34];
    int c0 = blockIdx.x * 32, r0 = blockIdx.y * 32;
    int x = threadIdx.x, y = threadIdx.y;
#pragma unroll
    for (int i = 0; i < 32; i += 8) {
        size_t o = (size_t)(r0 + y + i) * HDTOT + (c0 + x);
        t0[y + i][x] = sh[o];
        t1[y + i][x] = sl[o];
    }
    __syncthreads();
#pragma unroll
    for (int i = 0; i < 32; i += 8) {
        size_t o = (size_t)(c0 + y + i) * S + (r0 + x);
        th[o] = t0[x][y + i];
        tl[o] = t1[x][y + i];
    }
}

// ---------------- generic split-bf16 GEMM (QKV projections + output proj) ----------------
#define GEMM_SMEM_BYTES 98304

struct GemmSet {
    const bf16 *Bh, *Bl;
    const float *bias;
    float *C;
    bf16 *Ch, *Cl;
};
struct GemmSets { GemmSet s[3]; };

__global__ __launch_bounds__(256)
void gemm_bf3(const bf16* __restrict__ Ah, const bf16* __restrict__ Al, int lda,
              GemmSets sets, int nsets, int ldb,
              int ldc, int K, int mode)
{
    extern __shared__ char smdyn[];
    __shared__ float bS[128];
    const uint32_t smb = smem_u32(smdyn);
    const int tid = threadIdx.x, lane = tid & 31, wid = tid >> 5;
    const int m0 = blockIdx.y * 128, n0 = blockIdx.x * 128;
    const int wm = (wid >> 2) * 64, wn = (wid & 3) * 32;

    GemmSet st = sets.s[nsets > 1 ? blockIdx.z : 0];
    if (tid < 128) bS[tid] = st.bias ? st.bias[n0 + tid] : 0.f;

    const int idr = tid >> 1;
    const int idc = (tid & 1) * 2;
    const uint32_t swl = (idr >> 1) & 3;
    const uint32_t s0 = idr * 64 + ((idc ^ swl) << 4);
    const uint32_t s1 = idr * 64 + (((idc + 1) ^ swl) << 4);
    const bf16* gAh = Ah + (size_t)(m0 + idr) * lda + idc * 8;
    const bf16* gAl = Al + (size_t)(m0 + idr) * lda + idc * 8;
    const bf16* gBh = st.Bh + (size_t)(n0 + idr) * ldb + idc * 8;
    const bf16* gBl = st.Bl + (size_t)(n0 + idr) * ldb + idc * 8;

#define ISSUE(stg, kt) do {                                                    \
        uint32_t _b = smb + (stg) * 32768;                                     \
        cp16(_b +         s0, gAh + (kt)); cp16(_b +         s1, gAh + (kt) + 8); \
        cp16(_b +  8192 + s0, gAl + (kt)); cp16(_b +  8192 + s1, gAl + (kt) + 8); \
        cp16(_b + 16384 + s0, gBh + (kt)); cp16(_b + 16384 + s1, gBh + (kt) + 8); \
        cp16(_b + 24576 + s0, gBl + (kt)); cp16(_b + 24576 + s1, gBl + (kt) + 8); \
        CP_COMMIT();                                                           \
    } while (0)

    float c[4][4][4];
#pragma unroll
    for (int i = 0; i < 4; ++i)
#pragma unroll
        for (int j = 0; j < 4; ++j)
#pragma unroll
            for (int r = 0; r < 4; ++r) c[i][j][r] = 0.f;

    const int arow_l = lane & 15;
    const int achk_l = lane >> 4;
    const int brow_l = (lane & 7) + ((lane >> 4) << 3);
    const int bchk_l = (lane >> 3) & 1;

    const int nk = K / 32;
    ISSUE(0, 0);
    ISSUE(1, 32);

    for (int kt = 0; kt < nk; ++kt) {
        if (kt + 2 < nk) {
            ISSUE((kt + 2) % 3, (kt + 2) * 32);
            asm volatile("cp.async.wait_group 2;" ::: "memory");
        } else if (kt + 1 < nk) {
            asm volatile("cp.async.wait_group 1;" ::: "memory");
        } else {
            asm volatile("cp.async.wait_group 0;" ::: "memory");
        }
        __syncthreads();

        const uint32_t base = smb + (kt % 3) * 32768;
#pragma unroll
        for (int kk = 0; kk < 2; ++kk) {
            const int c0 = kk * 2;
            uint32_t a_h[4][4], a_l[4][4];
            const int ac = c0 + achk_l;
#pragma unroll
            for (int i = 0; i < 4; ++i) {
                int row = wm + i * 16 + arow_l;
                uint32_t ph = row * 64 + ((ac ^ ((row >> 1) & 3)) << 4);
                LDSM4(a_h[i], base + ph);
                LDSM4(a_l[i], base + 8192 + ph);
            }
            uint32_t b_h[4][2], b_l[4][2];
            const int bc = c0 + bchk_l;
#pragma unroll
            for (int j2 = 0; j2 < 2; ++j2) {
                int row = wn + j2 * 16 + brow_l;
                uint32_t ph = row * 64 + ((bc ^ ((row >> 1) & 3)) << 4);
                uint32_t r[4];
                LDSM4(r, base + 16384 + ph);
                b_h[2 * j2][0] = r[0]; b_h[2 * j2][1] = r[1];
                b_h[2 * j2 + 1][0] = r[2]; b_h[2 * j2 + 1][1] = r[3];
                LDSM4(r, base + 24576 + ph);
                b_l[2 * j2][0] = r[0]; b_l[2 * j2][1] = r[1];
                b_l[2 * j2 + 1][0] = r[2]; b_l[2 * j2 + 1][1] = r[3];
            }
#pragma unroll
            for (int i = 0; i < 4; ++i)
#pragma unroll
                for (int j = 0; j < 4; ++j) {
                    MMA(c[i][j], a_h[i], b_h[j][0], b_h[j][1]);
                    MMA(c[i][j], a_h[i], b_l[j][0], b_l[j][1]);
                    MMA(c[i][j], a_l[i], b_h[j][0], b_h[j][1]);
                }
        }
        __syncthreads();
    }

#pragma unroll
    for (int i = 0; i < 4; ++i) {
        int r0 = m0 + wm + i * 16 + (lane >> 2);
#pragma unroll
        for (int j = 0; j < 4; ++j) {
            int cb = wn + j * 8 + (lane & 3) * 2;
            float b0 = bS[cb], b1 = bS[cb + 1];
            float x0 = c[i][j][0] + b0, x1 = c[i][j][1] + b1;
            float x2 = c[i][j][2] + b0, x3 = c[i][j][3] + b1;
            if (mode == 0) {
                float2 v0 = { x0, x1 }, v1 = { x2, x3 };
                *(float2*)&st.C[(size_t)r0 * ldc + n0 + cb] = v0;
                *(float2*)&st.C[(size_t)(r0 + 8) * ldc + n0 + cb] = v1;
            } else {
                bf16 h0 = __float2bfloat16_rn(x0), h1 = __float2bfloat16_rn(x1);
                bf16 h2 = __float2bfloat16_rn(x2), h3 = __float2bfloat16_rn(x3);
                *(__nv_bfloat162*)&st.Ch[(size_t)r0 * ldc + n0 + cb] = __halves2bfloat162(h0, h1);
                *(__nv_bfloat162*)&st.Cl[(size_t)r0 * ldc + n0 + cb] = __halves2bfloat162(
                    __float2bfloat16_rn(x0 - __bfloat162float(h0)),
                    __float2bfloat16_rn(x1 - __bfloat162float(h1)));
                *(__nv_bfloat162*)&st.Ch[(size_t)(r0 + 8) * ldc + n0 + cb] = __halves2bfloat162(h2, h3);
                *(__nv_bfloat162*)&st.Cl[(size_t)(r0 + 8) * ldc + n0 + cb] = __halves2bfloat162(
                    __float2bfloat16_rn(x2 - __bfloat162float(h2)),
                    __float2bfloat16_rn(x3 - __bfloat162float(h3)));
            }
        }
    }
#undef ISSUE
}

// ---------------- scores GEMM: writes E=exp(s*scale) + per-row stats via atomics ----------------
__global__ __launch_bounds__(256)
void gemm_scores(const bf16* __restrict__ Ah, const bf16* __restrict__ Al,
                 const bf16* __restrict__ Bh, const bf16* __restrict__ Bl,
                 float* __restrict__ C, float alpha)
{
    extern __shared__ char smdyn[];
    const uint32_t smb = smem_u32(smdyn);
    const int tid = threadIdx.x, lane = tid & 31, wid = tid >> 5;
    const int h = blockIdx.z;
    const int m0 = blockIdx.y * 128, n0 = blockIdx.x * 128;
    const int wm = (wid >> 2) * 64, wn = (wid & 3) * 32;
    const int rel = (int)blockIdx.x - (int)blockIdx.y;

    Ah += (size_t)h * HDIM;  Al += (size_t)h * HDIM;
    Bh += (size_t)h * HDIM;  Bl += (size_t)h * HDIM;
    C  += (size_t)h * S * S;

    const int idr = tid >> 1;
    const int idc = (tid & 1) * 2;
    const uint32_t swl = (idr >> 1) & 3;
    const uint32_t s0 = idr * 64 + ((idc ^ swl) << 4);
    const uint32_t s1 = idr * 64 + (((idc + 1) ^ swl) << 4);
    const bf16* gAh = Ah + (size_t)(m0 + idr) * HDTOT + idc * 8;
    const bf16* gAl = Al + (size_t)(m0 + idr) * HDTOT + idc * 8;
    const bf16* gBh = Bh + (size_t)(n0 + idr) * HDTOT + idc * 8;
    const bf16* gBl = Bl + (size_t)(n0 + idr) * HDTOT + idc * 8;

#define ISSUE_S(stg, kt) do {                                                  \
        uint32_t _b = smb + (stg) * 32768;                                     \
        cp16(_b +         s0, gAh + (kt)); cp16(_b +         s1, gAh + (kt) + 8); \
        cp16(_b +  8192 + s0, gAl + (kt)); cp16(_b +  8192 + s1, gAl + (kt) + 8); \
        cp16(_b + 16384 + s0, gBh + (kt)); cp16(_b + 16384 + s1, gBh + (kt) + 8); \
        cp16(_b + 24576 + s0, gBl + (kt)); cp16(_b + 24576 + s1, gBl + (kt) + 8); \
        CP_COMMIT();                                                           \
    } while (0)

    float c[4][4][4];
#pragma unroll
    for (int i = 0; i < 4; ++i)
#pragma unroll
        for (int j = 0; j < 4; ++j)
#pragma unroll
            for (int r = 0; r < 4; ++r) c[i][j][r] = 0.f;

    const int arow_l = lane & 15;
    const int achk_l = lane >> 4;
    const int brow_l = (lane & 7) + ((lane >> 4) << 3);
    const int bchk_l = (lane >> 3) & 1;

    ISSUE_S(0, 0);
    ISSUE_S(1, 32);
    for (int kt = 0; kt < 4; ++kt) {
        if (kt + 2 < 4) {
            ISSUE_S((kt + 2) % 3, (kt + 2) * 32);
            asm volatile("cp.async.wait_group 2;" ::: "memory");
        } else if (kt + 1 < 4) {
            asm volatile("cp.async.wait_group 1;" ::: "memory");
        } else {
            asm volatile("cp.async.wait_group 0;" ::: "memory");
        }
        __syncthreads();
        const uint32_t base = smb + (kt % 3) * 32768;
#pragma unroll
        for (int kk = 0; kk < 2; ++kk) {
            const int c0 = kk * 2;
            uint32_t a_h[4][4], a_l[4][4];
            const int ac = c0 + achk_l;
#pragma unroll
            for (int i = 0; i < 4; ++i) {
                int row = wm + i * 16 + arow_l;
                uint32_t ph = row * 64 + ((ac ^ ((row >> 1) & 3)) << 4);
                LDSM4(a_h[i], base + ph);
                LDSM4(a_l[i], base + 8192 + ph);
            }
            uint32_t b_h[4][2], b_l[4][2];
            const int bc = c0 + bchk_l;
#pragma unroll
            for (int j2 = 0; j2 < 2; ++j2) {
                int row = wn + j2 * 16 + brow_l;
                uint32_t ph = row * 64 + ((bc ^ ((row >> 1) & 3)) << 4);
                uint32_t r[4];
                LDSM4(r, base + 16384 + ph);
                b_h[2 * j2][0] = r[0]; b_h[2 * j2][1] = r[1];
                b_h[2 * j2 + 1][0] = r[2]; b_h[2 * j2 + 1][1] = r[3];
                LDSM4(r, base + 24576 + ph);
                b_l[2 * j2][0] = r[0]; b_l[2 * j2][1] = r[1];
                b_l[2 * j2 + 1][0] = r[2]; b_l[2 * j2 + 1][1] = r[3];
            }
#pragma unroll
            for (int i = 0; i < 4; ++i)
#pragma unroll
                for (int j = 0; j < 4; ++j) {
                    MMA(c[i][j], a_h[i], b_h[j][0], b_h[j][1]);
                    MMA(c[i][j], a_h[i], b_l[j][0], b_l[j][1]);
                    MMA(c[i][j], a_l[i], b_h[j][0], b_h[j][1]);
                }
        }
        __syncthreads();
    }

    // epilogue: E = exp(alpha*s), store, and per-row stats via shfl + atomics
#pragma unroll
    for (int i = 0; i < 4; ++i) {
        const int rl0 = wm + i * 16 + (lane >> 2);   // local row (first of pair)
        float mb0 = 0.f, sb0 = 0.f, mb8 = 0.f, sb8 = 0.f;
        float mc0 = 0.f, sc0 = 0.f, mc8 = 0.f, sc8 = 0.f;
#pragma unroll
        for (int j = 0; j < 4; ++j) {
            const int cb = wn + j * 8 + (lane & 3) * 2;
            float E0 = __expf(c[i][j][0] * alpha);
            float E1 = __expf(c[i][j][1] * alpha);
            float E2 = __expf(c[i][j][2] * alpha);
            float E3 = __expf(c[i][j][3] * alpha);
            float2 v0 = { E0, E1 }, v1 = { E2, E3 };
            *(float2*)&C[(size_t)(m0 + rl0) * S + n0 + cb] = v0;
            *(float2*)&C[(size_t)(m0 + rl0 + 8) * S + n0 + cb] = v1;
            mb0 = fmaxf(mb0, fmaxf(E0, E1)); sb0 += E0 + E1;
            mb8 = fmaxf(mb8, fmaxf(E2, E3)); sb8 += E2 + E3;
            if (rel == 0) {
                float a0 = (cb     <= rl0)     ? E0 : 0.f;
                float a1 = (cb + 1 <= rl0)     ? E1 : 0.f;
                float a2 = (cb     <= rl0 + 8) ? E2 : 0.f;
                float a3 = (cb + 1 <= rl0 + 8) ? E3 : 0.f;
                mc0 = fmaxf(mc0, fmaxf(a0, a1)); sc0 += a0 + a1;
                mc8 = fmaxf(mc8, fmaxf(a2, a3)); sc8 += a2 + a3;
            }
        }
#pragma unroll
        for (int o = 1; o <= 2; o <<= 1) {
            mb0 = fmaxf(mb0, __shfl_xor_sync(0xffffffffu, mb0, o));
            sb0 += __shfl_xor_sync(0xffffffffu, sb0, o);
            mb8 = fmaxf(mb8, __shfl_xor_sync(0xffffffffu, mb8, o));
            sb8 += __shfl_xor_sync(0xffffffffu, sb8, o);
            mc0 = fmaxf(mc0, __shfl_xor_sync(0xffffffffu, mc0, o));
            sc0 += __shfl_xor_sync(0xffffffffu, sc0, o);
            mc8 = fmaxf(mc8, __shfl_xor_sync(0xffffffffu, mc8, o));
            sc8 += __shfl_xor_sync(0xffffffffu, sc8, o);
        }
        if ((lane & 3) == 0) {
            const size_t r0 = (size_t)h * S + m0 + rl0, r8 = r0 + 8;
            atomicMax((int*)&g_EmaxB[r0], __float_as_int(mb0));
            atomicAdd(&g_LB[r0], sb0);
            atomicMax((int*)&g_EmaxB[r8], __float_as_int(mb8));
            atomicAdd(&g_LB[r8], sb8);
            if (rel < 0) {
                atomicMax((int*)&g_EmaxC[r0], __float_as_int(mb0));
                atomicAdd(&g_LC[r0], sb0);
                atomicMax((int*)&g_EmaxC[r8], __float_as_int(mb8));
                atomicAdd(&g_LC[r8], sb8);
            } else if (rel == 0) {
                atomicMax((int*)&g_EmaxC[r0], __float_as_int(mc0));
                atomicAdd(&g_LC[r0], sc0);
                atomicMax((int*)&g_EmaxC[r8], __float_as_int(mc8));
                atomicAdd(&g_LC[r8], sc8);
            }
        }
    }
#undef ISSUE_S
}

// ---------------- stats init / finalize ----------------
__global__ __launch_bounds__(256)
void zero_stats() {
    int i = blockIdx.x * 256 + threadIdx.x;
    g_EmaxB[i] = 0.f; g_LB[i] = 0.f; g_EmaxC[i] = 0.f; g_LC[i] = 0.f;
}
__global__ __launch_bounds__(256)
void finalize_k12() {
    int i = blockIdx.x * 256 + threadIdx.x;
    float Eb = g_EmaxB[i], Lb = g_LB[i], Ec = g_EmaxC[i], Lc = g_LC[i];
    float dinv = 1.f / (Lc + 3.f * Lb);
    float k1 = 3.f * Eb / Lb * dinv;
    float k2 = k1 + Ec / Lc * dinv;
    g_K12[i] = make_float2(k1, k2);
}

// ---------------- AV GEMM: A = on-the-fly weights from E fp32, B = V^T ----------------
// smem: 2 stages x (Eraw 16KB @0, Bh 8KB @16384, Bl 8KB @24576) = 64KB; conv double 32KB @65536.
#define AV_SMEM_BYTES 98304

__global__ __launch_bounds__(256)
void gemm_av(const float* __restrict__ E,
             const bf16* __restrict__ Bh, const bf16* __restrict__ Bl,
             bf16* __restrict__ Ch, bf16* __restrict__ Cl)
{
    extern __shared__ char smdyn[];
    __shared__ float2 k12s[128];
    const uint32_t smb = smem_u32(smdyn);
    const int tid = threadIdx.x, lane = tid & 31, wid = tid >> 5;
    const int h = blockIdx.z;
    const int m0 = blockIdx.y * 128;
    const int wm = (wid >> 2) * 64, wn = (wid & 3) * 32;

    E  += (size_t)h * S * S;
    Bh += (size_t)h * HDIM * S;
    Bl += (size_t)h * HDIM * S;
    Ch += (size_t)h * HDIM;
    Cl += (size_t)h * HDIM;

    if (tid < 128) k12s[tid] = g_K12[(size_t)h * S + m0 + tid];

    // raw E loader: row = tid>>1, half = tid&1 (16 floats = 4x16B)
    const float* gE = E + (size_t)(m0 + (tid >> 1)) * S + (tid & 1) * 16;
    const uint32_t rawoff = (tid >> 1) * 128 + (tid & 1) * 64;
    // B loader (bf16, 64B rows, swizzled)
    const int idr = tid >> 1;
    const int idc = (tid & 1) * 2;
    const uint32_t swl = (idr >> 1) & 3;
    const uint32_t s0 = idr * 64 + ((idc ^ swl) << 4);
    const uint32_t s1 = idr * 64 + (((idc + 1) ^ swl) << 4);
    const bf16* gBh = Bh + (size_t)idr * S + idc * 8;
    const bf16* gBl = Bl + (size_t)idr * S + idc * 8;

#define ISSUE_AV(stg, kt) do {                                                 \
        uint32_t _b = smb + (stg) * 32768;                                     \
        cp16(_b + rawoff +  0, gE + (kt) +  0);                                \
        cp16(_b + rawoff + 16, gE + (kt) +  4);                                \
        cp16(_b + rawoff + 32, gE + (kt) +  8);                                \
        cp16(_b + rawoff + 48, gE + (kt) + 12);                                \
        cp16(_b + 16384 + s0, gBh + (kt)); cp16(_b + 16384 + s1, gBh + (kt) + 8); \
        cp16(_b + 24576 + s0, gBl + (kt)); cp16(_b + 24576 + s1, gBl + (kt) + 8); \
        CP_COMMIT();                                                           \
    } while (0)

    float c[4][4][4];
#pragma unroll
    for (int i = 0; i < 4; ++i)
#pragma unroll
        for (int j = 0; j < 4; ++j)
#pragma unroll
            for (int r = 0; r < 4; ++r) c[i][j][r] = 0.f;

    const int arow_l = lane & 15;
    const int achk_l = lane >> 4;
    const int brow_l = (lane & 7) + ((lane >> 4) << 3);
    const int bchk_l = (lane >> 3) & 1;
    const int cp = lane & 15;          // column-pair index for convert
    const int rsub = lane >> 4;        // row sub-select for convert

    const int nk = S / 32;             // 64
    ISSUE_AV(0, 0);
    ISSUE_AV(1, 32);

    for (int kt = 0; kt < nk; ++kt) {
        if (kt + 1 < nk) asm volatile("cp.async.wait_group 1;" ::: "memory");
        else             asm volatile("cp.async.wait_group 0;" ::: "memory");
        __syncthreads();

        // convert raw E -> weights, split hi/lo into conv[kt&1]
        {
            char* rb = smdyn + (kt & 1) * 32768;
            char* ch = smdyn + 65536 + (kt & 1) * 16384;
            char* cl = ch + 8192;
#pragma unroll
            for (int it = 0; it < 8; ++it) {
                const int r = wid * 16 + it * 2 + rsub;
                float2 e2 = *(float2*)(rb + r * 128 + cp * 8);
                const int colg = kt * 32 + 2 * cp;
                const int rowg = m0 + r;
                float2 kk = k12s[r];
                float w0 = e2.x * ((colg     <= rowg) ? kk.y : kk.x);
                float w1 = e2.y * ((colg + 1 <= rowg) ? kk.y : kk.x);
                bf16 h0 = __float2bfloat16_rn(w0);
                bf16 h1 = __float2bfloat16_rn(w1);
                const uint32_t byo = r * 64 + ((((uint32_t)cp >> 2) ^ (((uint32_t)r >> 1) & 3)) << 4) + (cp & 3) * 4;
                *(__nv_bfloat162*)(ch + byo) = __halves2bfloat162(h0, h1);
                *(__nv_bfloat162*)(cl + byo) = __halves2bfloat162(
                    __float2bfloat16_rn(w0 - __bfloat162float(h0)),
                    __float2bfloat16_rn(w1 - __bfloat162float(h1)));
            }
        }
        __syncthreads();

        const uint32_t base  = smb + (kt & 1) * 32768;
        const uint32_t convA = smb + 65536 + (kt & 1) * 16384;
#pragma unroll
        for (int kk = 0; kk < 2; ++kk) {
            const int c0 = kk * 2;
            uint32_t a_h[4][4], a_l[4][4];
            const int ac = c0 + achk_l;
#pragma unroll
            for (int i = 0; i < 4; ++i) {
                int row = wm + i * 16 + arow_l;
                uint32_t ph = row * 64 + ((ac ^ ((row >> 1) & 3)) << 4);
                LDSM4(a_h[i], convA + ph);
                LDSM4(a_l[i], convA + 8192 + ph);
            }
            uint32_t b_h[4][2], b_l[4][2];
            const int bc = c0 + bchk_l;
#pragma unroll
            for (int j2 = 0; j2 < 2; ++j2) {
                int row = wn + j2 * 16 + brow_l;
                uint32_t ph = row * 64 + ((bc ^ ((row >> 1) & 3)) << 4);
                uint32_t r[4];
                LDSM4(r, base + 16384 + ph);
                b_h[2 * j2][0] = r[0]; b_h[2 * j2][1] = r[1];
                b_h[2 * j2 + 1][0] = r[2]; b_h[2 * j2 + 1][1] = r[3];
                LDSM4(r, base + 24576 + ph);
                b_l[2 * j2][0] = r[0]; b_l[2 * j2][1] = r[1];
                b_l[2 * j2 + 1][0] = r[2]; b_l[2 * j2 + 1][1] = r[3];
            }
#pragma unroll
            for (int i = 0; i < 4; ++i)
#pragma unroll
                for (int j = 0; j < 4; ++j) {
                    MMA(c[i][j], a_h[i], b_h[j][0], b_h[j][1]);
                    MMA(c[i][j], a_h[i], b_l[j][0], b_l[j][1]);
                    MMA(c[i][j], a_l[i], b_h[j][0], b_h[j][1]);
                }
        }
        __syncthreads();                       // stage kt&1 free for reuse
        if (kt + 2 < nk) ISSUE_AV(kt & 1, (kt + 2) * 32);
    }

    // epilogue: split hi/lo store
#pragma unroll
    for (int i = 0; i < 4; ++i) {
        int r0 = m0 + wm + i * 16 + (lane >> 2);
#pragma unroll
        for (int j = 0; j < 4; ++j) {
            int cb = wn + j * 8 + (lane & 3) * 2;
            float x0 = c[i][j][0], x1 = c[i][j][1];
            float x2 = c[i][j][2], x3 = c[i][j][3];
            bf16 h0 = __float2bfloat16_rn(x0), h1 = __float2bfloat16_rn(x1);
            bf16 h2 = __float2bfloat16_rn(x2), h3 = __float2bfloat16_rn(x3);
            *(__nv_bfloat162*)&Ch[(size_t)r0 * HDTOT + cb] = __halves2bfloat162(h0, h1);
            *(__nv_bfloat162*)&Cl[(size_t)r0 * HDTOT + cb] = __halves2bfloat162(
                __float2bfloat16_rn(x0 - __bfloat162float(h0)),
                __float2bfloat16_rn(x1 - __bfloat162float(h1)));
            *(__nv_bfloat162*)&Ch[(size_t)(r0 + 8) * HDTOT + cb] = __halves2bfloat162(h2, h3);
            *(__nv_bfloat162*)&Cl[(size_t)(r0 + 8) * HDTOT + cb] = __halves2bfloat162(
                __float2bfloat16_rn(x2 - __bfloat162float(h2)),
                __float2bfloat16_rn(x3 - __bfloat162float(h3)));
        }
    }
#undef ISSUE_AV
}

// ---------------- launch ----------------
extern "C" void kernel_launch(void* const* d_in, const int* in_sizes, int n_in,
                              void* d_out, int out_size)
{
    (void)in_sizes; (void)n_in; (void)out_size;
    const float* X  = (const float*)d_in[0];
    const float* qw = (const float*)d_in[1];
    const float* qb = (const float*)d_in[2];
    const float* kw = (const float*)d_in[3];
    const float* kb = (const float*)d_in[4];
    const float* vw = (const float*)d_in[5];
    const float* vb = (const float*)d_in[6];
    const float* ow = (const float*)d_in[7];
    const float* ob = (const float*)d_in[8];
    float* out = (float*)d_out;

    bf16 *xh, *xl, *qwh, *qwl, *kwh, *kwl, *vwh, *vwl, *owh, *owl;
    bf16 *qh, *ql, *kh, *kl, *vh, *vl, *vth, *vtl, *ath, *atl;
    float *gs;
    cudaGetSymbolAddress((void**)&xh,  g_Xh);  cudaGetSymbolAddress((void**)&xl,  g_Xl);
    cudaGetSymbolAddress((void**)&qwh, g_qwh); cudaGetSymbolAddress((void**)&qwl, g_qwl);
    cudaGetSymbolAddress((void**)&kwh, g_kwh); cudaGetSymbolAddress((void**)&kwl, g_kwl);
    cudaGetSymbolAddress((void**)&vwh, g_vwh); cudaGetSymbolAddress((void**)&vwl, g_vwl);
    cudaGetSymbolAddress((void**)&owh, g_owh); cudaGetSymbolAddress((void**)&owl, g_owl);
    cudaGetSymbolAddress((void**)&qh,  g_qh);  cudaGetSymbolAddress((void**)&ql,  g_ql);
    cudaGetSymbolAddress((void**)&kh,  g_kh);  cudaGetSymbolAddress((void**)&kl,  g_kl);
    cudaGetSymbolAddress((void**)&vh,  g_vh);  cudaGetSymbolAddress((void**)&vl,  g_vl);
    cudaGetSymbolAddress((void**)&vth, g_vth); cudaGetSymbolAddress((void**)&vtl, g_vtl);
    cudaGetSymbolAddress((void**)&ath, g_ath); cudaGetSymbolAddress((void**)&atl, g_atl);
    cudaGetSymbolAddress((void**)&gs,  g_scores);

    cudaFuncSetAttribute(gemm_bf3,    cudaFuncAttributeMaxDynamicSharedMemorySize, GEMM_SMEM_BYTES);
    cudaFuncSetAttribute(gemm_scores, cudaFuncAttributeMaxDynamicSharedMemorySize, GEMM_SMEM_BYTES);
    cudaFuncSetAttribute(gemm_av,     cudaFuncAttributeMaxDynamicSharedMemorySize, AV_SMEM_BYTES);

    const float scale = 0.08838834764831843f;   // 1/sqrt(128)
    dim3 gblk(256);

    // split inputs + weights to bf16 hi/lo
    {
        SplitArgs sa;
        sa.s[0] = X;  sa.h[0] = xh;  sa.l[0] = xl;
        sa.s[1] = qw; sa.h[1] = qwh; sa.l[1] = qwl;
        sa.s[2] = kw; sa.h[2] = kwh; sa.l[2] = kwl;
        sa.s[3] = vw; sa.h[3] = vwh; sa.l[3] = vwl;
        sa.s[4] = ow; sa.h[4] = owh; sa.l[4] = owl;
        split5<<<dim3(S * HID / 4 / 256, 5), dim3(256)>>>(sa);
    }

    // zero softmax stats
    zero_stats<<<NHEAD * S / 256, 256>>>();

    // Q/K/V projections -> split bf16
    {
        GemmSets gsz = {};
        gsz.s[0] = { qwh, qwl, qb, nullptr, qh, ql };
        gsz.s[1] = { kwh, kwl, kb, nullptr, kh, kl };
        gsz.s[2] = { vwh, vwl, vb, nullptr, vh, vl };
        gemm_bf3<<<dim3(16, 16, 3), gblk, GEMM_SMEM_BYTES>>>(
            xh, xl, HID, gsz, 3, HID, HDTOT, HID, 1);
    }

    // transpose V hi/lo
    transpose_b16<<<dim3(HDTOT / 32, S / 32), dim3(32, 8)>>>(vh, vl, vth, vtl);

    // scores: E = exp(scale * Q K^T) + row stats
    gemm_scores<<<dim3(16, 16, NHEAD), gblk, GEMM_SMEM_BYTES>>>(
        qh, ql, kh, kl, gs, scale);

    // finalize per-row weight constants
    finalize_k12<<<NHEAD * S / 256, 256>>>();

    // attn = W @ V with on-the-fly weight construction
    gemm_av<<<dim3(1, 16, NHEAD), gblk, AV_SMEM_BYTES>>>(
        gs, vth, vtl, ath, atl);

    // output projection (fp32 to d_out)
    {
        GemmSets gsz = {};
        gsz.s[0] = { owh, owl, ob, out, nullptr, nullptr };
        gemm_bf3<<<dim3(16, 16, 1), gblk, GEMM_SMEM_BYTES>>>(
            ath, atl, HDTOT, gsz, 1, HDTOT, HID, HDTOT, 0);
    }
}

// round 17
// speedup vs baseline: 1.1048x; 1.1048x over previous
#include <cuda_runtime.h>
#include <cuda_bf16.h>
#include <stdint.h>
#include <math.h>

// Problem constants (fixed by setup_inputs)
#define S     2048
#define HID   2048
#define NHEAD 16
#define HDIM  128
#define HDTOT 2048
#define RING_REST 3.0f   // world_size - 1 identical non-causal ring steps

typedef __nv_bfloat16 bf16;

// ---------------- static device scratch ----------------
__device__ bf16  g_Xh [S * HID],     g_Xl [S * HID];
__device__ bf16  g_qwh[HDTOT * HID], g_qwl[HDTOT * HID];
__device__ bf16  g_kwh[HDTOT * HID], g_kwl[HDTOT * HID];
__device__ bf16  g_vwh[HDTOT * HID], g_vwl[HDTOT * HID];
__device__ bf16  g_owh[HID * HDTOT], g_owl[HID * HDTOT];
__device__ bf16  g_qh [S * HDTOT], g_ql [S * HDTOT];
__device__ bf16  g_kh [S * HDTOT], g_kl [S * HDTOT];
__device__ bf16  g_vh [S * HDTOT], g_vl [S * HDTOT];
__device__ bf16  g_vth[HDTOT * S], g_vtl[HDTOT * S];   // V transposed (H*D, S)
__device__ bf16  g_ath[S * HDTOT], g_atl[S * HDTOT];
__device__ float g_scores[(size_t)NHEAD * S * S];      // 256 MB
__device__ bf16  g_wh[(size_t)NHEAD * S * S];          // attention weights hi
__device__ bf16  g_wl[(size_t)NHEAD * S * S];          // attention weights lo

// ---------------- PTX helpers (base compute_103 features only) ----------------
__device__ __forceinline__ uint32_t smem_u32(const void* p) {
    uint32_t a;
    asm("{ .reg .u64 t; cvta.to.shared.u64 t, %1; cvt.u32.u64 %0, t; }" : "=r"(a) : "l"(p));
    return a;
}
__device__ __forceinline__ void cp16(uint32_t s, const void* g) {
    asm volatile("cp.async.cg.shared.global [%0], [%1], 16;" :: "r"(s), "l"(g));
}
#define CP_COMMIT() asm volatile("cp.async.commit_group;" ::: "memory")

#define LDSM4(r, addr) \
    asm volatile("ldmatrix.sync.aligned.m8n8.x4.shared.b16 {%0,%1,%2,%3}, [%4];" \
        : "=r"((r)[0]), "=r"((r)[1]), "=r"((r)[2]), "=r"((r)[3]) : "r"(addr))

#define MMA(cc, aa, b0, b1) \
    asm volatile("mma.sync.aligned.m16n8k16.row.col.f32.bf16.bf16.f32 " \
        "{%0,%1,%2,%3}, {%4,%5,%6,%7}, {%8,%9}, {%0,%1,%2,%3};" \
        : "+f"((cc)[0]), "+f"((cc)[1]), "+f"((cc)[2]), "+f"((cc)[3]) \
        : "r"((aa)[0]), "r"((aa)[1]), "r"((aa)[2]), "r"((aa)[3]), "r"(b0), "r"(b1))

// ---------------- merged split kernel: 5 fp32 tensors -> bf16 hi/lo ----------------
struct SplitArgs {
    const float* s[5];
    bf16* h[5];
    bf16* l[5];
};

__global__ __launch_bounds__(256)
void split5(SplitArgs a) {
    const int set = blockIdx.y;
    const int i = blockIdx.x * 256 + threadIdx.x;
    float4 v = ((const float4*)a.s[set])[i];
    bf16 h0 = __float2bfloat16_rn(v.x), h1 = __float2bfloat16_rn(v.y);
    bf16 h2 = __float2bfloat16_rn(v.z), h3 = __float2bfloat16_rn(v.w);
    bf16 l0 = __float2bfloat16_rn(v.x - __bfloat162float(h0));
    bf16 l1 = __float2bfloat16_rn(v.y - __bfloat162float(h1));
    bf16 l2 = __float2bfloat16_rn(v.z - __bfloat162float(h2));
    bf16 l3 = __float2bfloat16_rn(v.w - __bfloat162float(h3));
    ((__nv_bfloat162*)a.h[set])[2 * i]     = __halves2bfloat162(h0, h1);
    ((__nv_bfloat162*)a.h[set])[2 * i + 1] = __halves2bfloat162(h2, h3);
    ((__nv_bfloat162*)a.l[set])[2 * i]     = __halves2bfloat162(l0, l1);
    ((__nv_bfloat162*)a.l[set])[2 * i + 1] = __halves2bfloat162(l2, l3);
}

// ---------------- bf16 transpose ----------------
__global__ __launch_bounds__(256)
void transpose_b16(const bf16* __restrict__ sh, const bf16* __restrict__ sl,
                   bf16* __restrict__ th, bf16* __restrict__ tl) {
    __shared__ bf16 t0[32][34];
    __shared__ bf16 t1[32][34];
    int c0 = blockIdx.x * 32, r0 = blockIdx.y * 32;
    int x = threadIdx.x, y = threadIdx.y;
#pragma unroll
    for (int i = 0; i < 32; i += 8) {
        size_t o = (size_t)(r0 + y + i) * HDTOT + (c0 + x);
        t0[y + i][x] = sh[o];
        t1[y + i][x] = sl[o];
    }
    __syncthreads();
#pragma unroll
    for (int i = 0; i < 32; i += 8) {
        size_t o = (size_t)(c0 + y + i) * S + (r0 + x);
        th[o] = t0[x][y + i];
        tl[o] = t1[x][y + i];
    }
}

// ---------------- split-bf16 GEMM via mma.sync:  C = A*B^T + bias ----------------
// CTA tile 128x128, BK=32, 8 warps (2m x 4n), 3-stage cp.async pipeline (96KB smem).
#define GEMM_SMEM_BYTES 98304

struct GemmSet {
    const bf16 *Bh, *Bl;
    const float *bias;
    float *C;
    bf16 *Ch, *Cl;
};
struct GemmSets { GemmSet s[3]; };

__global__ __launch_bounds__(256)
void gemm_bf3(const bf16* __restrict__ Ah, const bf16* __restrict__ Al, int lda, long long sAz,
              GemmSets sets, int nsets, int ldb, long long sBz,
              int ldc, long long sCz,
              int K, float alpha, int mode)
{
    extern __shared__ char smdyn[];
    __shared__ float bS[128];
    const uint32_t smb = smem_u32(smdyn);
    const int tid = threadIdx.x, lane = tid & 31, wid = tid >> 5;
    const int m0 = blockIdx.y * 128, n0 = blockIdx.x * 128;
    const int wm = (wid >> 2) * 64, wn = (wid & 3) * 32;

    GemmSet st = sets.s[nsets > 1 ? blockIdx.z : 0];
    Ah += (size_t)blockIdx.z * sAz;
    Al += (size_t)blockIdx.z * sAz;
    if (nsets == 1) {
        st.Bh += (size_t)blockIdx.z * sBz;
        st.Bl += (size_t)blockIdx.z * sBz;
        if (st.C)  st.C  += (size_t)blockIdx.z * sCz;
        if (st.Ch) { st.Ch += (size_t)blockIdx.z * sCz; st.Cl += (size_t)blockIdx.z * sCz; }
    }

    if (tid < 128) bS[tid] = st.bias ? st.bias[n0 + tid] : 0.f;

    const int idr = tid >> 1;
    const int idc = (tid & 1) * 2;
    const uint32_t swl = (idr >> 1) & 3;
    const uint32_t s0 = idr * 64 + ((idc ^ swl) << 4);
    const uint32_t s1 = idr * 64 + (((idc + 1) ^ swl) << 4);
    const bf16* gAh = Ah + (size_t)(m0 + idr) * lda + idc * 8;
    const bf16* gAl = Al + (size_t)(m0 + idr) * lda + idc * 8;
    const bf16* gBh = st.Bh + (size_t)(n0 + idr) * ldb + idc * 8;
    const bf16* gBl = st.Bl + (size_t)(n0 + idr) * ldb + idc * 8;

#define ISSUE(stg, kt) do {                                                    \
        uint32_t _b = smb + (stg) * 32768;                                     \
        cp16(_b +         s0, gAh + (kt)); cp16(_b +         s1, gAh + (kt) + 8); \
        cp16(_b +  8192 + s0, gAl + (kt)); cp16(_b +  8192 + s1, gAl + (kt) + 8); \
        cp16(_b + 16384 + s0, gBh + (kt)); cp16(_b + 16384 + s1, gBh + (kt) + 8); \
        cp16(_b + 24576 + s0, gBl + (kt)); cp16(_b + 24576 + s1, gBl + (kt) + 8); \
        CP_COMMIT();                                                           \
    } while (0)

    float c[4][4][4];
#pragma unroll
    for (int i = 0; i < 4; ++i)
#pragma unroll
        for (int j = 0; j < 4; ++j)
#pragma unroll
            for (int r = 0; r < 4; ++r) c[i][j][r] = 0.f;

    const int arow_l = lane & 15;
    const int achk_l = lane >> 4;
    const int brow_l = (lane & 7) + ((lane >> 4) << 3);
    const int bchk_l = (lane >> 3) & 1;

    const int nk = K / 32;
    ISSUE(0, 0);
    ISSUE(1, 32);

    for (int kt = 0; kt < nk; ++kt) {
        if (kt + 2 < nk) {
            ISSUE((kt + 2) % 3, (kt + 2) * 32);
            asm volatile("cp.async.wait_group 2;" ::: "memory");
        } else if (kt + 1 < nk) {
            asm volatile("cp.async.wait_group 1;" ::: "memory");
        } else {
            asm volatile("cp.async.wait_group 0;" ::: "memory");
        }
        __syncthreads();

        const uint32_t base = smb + (kt % 3) * 32768;
#pragma unroll
        for (int kk = 0; kk < 2; ++kk) {
            const int c0 = kk * 2;
            uint32_t a_h[4][4], a_l[4][4];
            const int ac = c0 + achk_l;
#pragma unroll
            for (int i = 0; i < 4; ++i) {
                int row = wm + i * 16 + arow_l;
                uint32_t ph = row * 64 + ((ac ^ ((row >> 1) & 3)) << 4);
                LDSM4(a_h[i], base + ph);
                LDSM4(a_l[i], base + 8192 + ph);
            }
            uint32_t b_h[4][2], b_l[4][2];
            const int bc = c0 + bchk_l;
#pragma unroll
            for (int j2 = 0; j2 < 2; ++j2) {
                int row = wn + j2 * 16 + brow_l;
                uint32_t ph = row * 64 + ((bc ^ ((row >> 1) & 3)) << 4);
                uint32_t r[4];
                LDSM4(r, base + 16384 + ph);
                b_h[2 * j2][0] = r[0]; b_h[2 * j2][1] = r[1];
                b_h[2 * j2 + 1][0] = r[2]; b_h[2 * j2 + 1][1] = r[3];
                LDSM4(r, base + 24576 + ph);
                b_l[2 * j2][0] = r[0]; b_l[2 * j2][1] = r[1];
                b_l[2 * j2 + 1][0] = r[2]; b_l[2 * j2 + 1][1] = r[3];
            }
#pragma unroll
            for (int i = 0; i < 4; ++i)
#pragma unroll
                for (int j = 0; j < 4; ++j) {
                    MMA(c[i][j], a_h[i], b_h[j][0], b_h[j][1]);
                    MMA(c[i][j], a_h[i], b_l[j][0], b_l[j][1]);
                    MMA(c[i][j], a_l[i], b_h[j][0], b_h[j][1]);
                }
        }
        __syncthreads();
    }

#pragma unroll
    for (int i = 0; i < 4; ++i) {
        int r0 = m0 + wm + i * 16 + (lane >> 2);
#pragma unroll
        for (int j = 0; j < 4; ++j) {
            int cb = wn + j * 8 + (lane & 3) * 2;
            float b0 = bS[cb], b1 = bS[cb + 1];
            float x0 = c[i][j][0] * alpha + b0, x1 = c[i][j][1] * alpha + b1;
            float x2 = c[i][j][2] * alpha + b0, x3 = c[i][j][3] * alpha + b1;
            if (mode == 0) {
                float2 v0 = { x0, x1 }, v1 = { x2, x3 };
                *(float2*)&st.C[(size_t)r0 * ldc + n0 + cb] = v0;
                *(float2*)&st.C[(size_t)(r0 + 8) * ldc + n0 + cb] = v1;
            } else {
                bf16 h0 = __float2bfloat16_rn(x0), h1 = __float2bfloat16_rn(x1);
                bf16 h2 = __float2bfloat16_rn(x2), h3 = __float2bfloat16_rn(x3);
                *(__nv_bfloat162*)&st.Ch[(size_t)r0 * ldc + n0 + cb] = __halves2bfloat162(h0, h1);
                *(__nv_bfloat162*)&st.Cl[(size_t)r0 * ldc + n0 + cb] = __halves2bfloat162(
                    __float2bfloat16_rn(x0 - __bfloat162float(h0)),
                    __float2bfloat16_rn(x1 - __bfloat162float(h1)));
                *(__nv_bfloat162*)&st.Ch[(size_t)(r0 + 8) * ldc + n0 + cb] = __halves2bfloat162(h2, h3);
                *(__nv_bfloat162*)&st.Cl[(size_t)(r0 + 8) * ldc + n0 + cb] = __halves2bfloat162(
                    __float2bfloat16_rn(x2 - __bfloat162float(h2)),
                    __float2bfloat16_rn(x3 - __bfloat162float(h3)));
            }
        }
    }
#undef ISSUE
}

// ---------------- ring-softmax (vectorized): scores fp32 -> weights bf16 hi/lo ----------------
// Each thread owns 8 CONTIGUOUS elements: 2x LDG.128 in, 2x STG.128 out (wh, wl).
__global__ __launch_bounds__(256)
void ring_softmax(const float* __restrict__ scores, bf16* __restrict__ wh, bf16* __restrict__ wl)
{
    const int row = blockIdx.x;
    const size_t off = ((size_t)blockIdx.y * S + row) * S;
    const int tid = threadIdx.x;
    const int j0 = tid * 8;

    const float4* p4 = (const float4*)(scores + off + j0);
    float4 va = p4[0], vb = p4[1];
    float v[8] = { va.x, va.y, va.z, va.w, vb.x, vb.y, vb.z, vb.w };

    float mB = -3.0e38f, mC = -3.0e38f;
#pragma unroll
    for (int t = 0; t < 8; ++t) {
        mB = fmaxf(mB, v[t]);
        if (j0 + t <= row) mC = fmaxf(mC, v[t]);
    }

    __shared__ float sm0[8], sm1[8];
    const int wid = tid >> 5, lid = tid & 31;
#pragma unroll
    for (int o = 16; o > 0; o >>= 1) {
        mB = fmaxf(mB, __shfl_xor_sync(0xffffffffu, mB, o));
        mC = fmaxf(mC, __shfl_xor_sync(0xffffffffu, mC, o));
    }
    if (lid == 0) { sm0[wid] = mB; sm1[wid] = mC; }
    __syncthreads();
    mB = sm0[0]; mC = sm1[0];
#pragma unroll
    for (int i = 1; i < 8; ++i) { mB = fmaxf(mB, sm0[i]); mC = fmaxf(mC, sm1[i]); }
    __syncthreads();

    float eb[8], ec[8];
    float sB = 0.f, sC = 0.f;
#pragma unroll
    for (int t = 0; t < 8; ++t) {
        eb[t] = __expf(v[t] - mB);
        ec[t] = (j0 + t <= row) ? __expf(v[t] - mC) : 0.f;
        sB += eb[t];
        sC += ec[t];
    }
#pragma unroll
    for (int o = 16; o > 0; o >>= 1) {
        sB += __shfl_xor_sync(0xffffffffu, sB, o);
        sC += __shfl_xor_sync(0xffffffffu, sC, o);
    }
    if (lid == 0) { sm0[wid] = sB; sm1[wid] = sC; }
    __syncthreads();
    sB = 0.f; sC = 0.f;
#pragma unroll
    for (int i = 0; i < 8; ++i) { sB += sm0[i]; sC += sm1[i]; }

    const float e     = __expf(mC - mB);
    const float cb    = RING_REST / (sB + 1e-8f);
    const float cc    = e / (sC + 1e-8f);
    const float invSe = 1.0f / (e * sC + RING_REST * sB + 1e-8f);

    __nv_bfloat162 H[4], L[4];
#pragma unroll
    for (int t2 = 0; t2 < 4; ++t2) {
        float w0 = (eb[2 * t2]     * cb + ec[2 * t2]     * cc) * invSe;
        float w1 = (eb[2 * t2 + 1] * cb + ec[2 * t2 + 1] * cc) * invSe;
        bf16 h0 = __float2bfloat16_rn(w0);
        bf16 h1 = __float2bfloat16_rn(w1);
        H[t2] = __halves2bfloat162(h0, h1);
        L[t2] = __halves2bfloat162(
            __float2bfloat16_rn(w0 - __bfloat162float(h0)),
            __float2bfloat16_rn(w1 - __bfloat162float(h1)));
    }
    *(uint4*)&wh[off + j0] = *(uint4*)H;
    *(uint4*)&wl[off + j0] = *(uint4*)L;
}

// ---------------- launch ----------------
extern "C" void kernel_launch(void* const* d_in, const int* in_sizes, int n_in,
                              void* d_out, int out_size)
{
    (void)in_sizes; (void)n_in; (void)out_size;
    const float* X  = (const float*)d_in[0];
    const float* qw = (const float*)d_in[1];
    const float* qb = (const float*)d_in[2];
    const float* kw = (const float*)d_in[3];
    const float* kb = (const float*)d_in[4];
    const float* vw = (const float*)d_in[5];
    const float* vb = (const float*)d_in[6];
    const float* ow = (const float*)d_in[7];
    const float* ob = (const float*)d_in[8];
    float* out = (float*)d_out;

    bf16 *xh, *xl, *qwh, *qwl, *kwh, *kwl, *vwh, *vwl, *owh, *owl;
    bf16 *qh, *ql, *kh, *kl, *vh, *vl, *vth, *vtl, *ath, *atl, *wh, *wl;
    float *gs;
    cudaGetSymbolAddress((void**)&xh,  g_Xh);  cudaGetSymbolAddress((void**)&xl,  g_Xl);
    cudaGetSymbolAddress((void**)&qwh, g_qwh); cudaGetSymbolAddress((void**)&qwl, g_qwl);
    cudaGetSymbolAddress((void**)&kwh, g_kwh); cudaGetSymbolAddress((void**)&kwl, g_kwl);
    cudaGetSymbolAddress((void**)&vwh, g_vwh); cudaGetSymbolAddress((void**)&vwl, g_vwl);
    cudaGetSymbolAddress((void**)&owh, g_owh); cudaGetSymbolAddress((void**)&owl, g_owl);
    cudaGetSymbolAddress((void**)&qh,  g_qh);  cudaGetSymbolAddress((void**)&ql,  g_ql);
    cudaGetSymbolAddress((void**)&kh,  g_kh);  cudaGetSymbolAddress((void**)&kl,  g_kl);
    cudaGetSymbolAddress((void**)&vh,  g_vh);  cudaGetSymbolAddress((void**)&vl,  g_vl);
    cudaGetSymbolAddress((void**)&vth, g_vth); cudaGetSymbolAddress((void**)&vtl, g_vtl);
    cudaGetSymbolAddress((void**)&ath, g_ath); cudaGetSymbolAddress((void**)&atl, g_atl);
    cudaGetSymbolAddress((void**)&gs,  g_scores);
    cudaGetSymbolAddress((void**)&wh,  g_wh);  cudaGetSymbolAddress((void**)&wl,  g_wl);

    cudaFuncSetAttribute(gemm_bf3, cudaFuncAttributeMaxDynamicSharedMemorySize, GEMM_SMEM_BYTES);

    const float scale = 0.08838834764831843f;   // 1/sqrt(128)
    dim3 gblk(256);

    // split inputs + weights to bf16 hi/lo (single launch, 5 sets)
    {
        SplitArgs sa;
        sa.s[0] = X;  sa.h[0] = xh;  sa.l[0] = xl;
        sa.s[1] = qw; sa.h[1] = qwh; sa.l[1] = qwl;
        sa.s[2] = kw; sa.h[2] = kwh; sa.l[2] = kwl;
        sa.s[3] = vw; sa.h[3] = vwh; sa.l[3] = vwl;
        sa.s[4] = ow; sa.h[4] = owh; sa.l[4] = owl;
        split5<<<dim3(S * HID / 4 / 256, 5), dim3(256)>>>(sa);
    }

    // merged Q/K/V projections -> split bf16
    {
        GemmSets gsz = {};
        gsz.s[0] = { qwh, qwl, qb, nullptr, qh, ql };
        gsz.s[1] = { kwh, kwl, kb, nullptr, kh, kl };
        gsz.s[2] = { vwh, vwl, vb, nullptr, vh, vl };
        gemm_bf3<<<dim3(16, 16, 3), gblk, GEMM_SMEM_BYTES>>>(
            xh, xl, HID, 0, gsz, 3, HID, 0, HDTOT, 0, HID, 1.0f, 1);
    }

    // transpose V hi/lo
    transpose_b16<<<dim3(HDTOT / 32, S / 32), dim3(32, 8)>>>(vh, vl, vth, vtl);

    // scores[h] = scale * Q_h @ K_h^T  (fp32 out)
    {
        GemmSets gsz = {};
        gsz.s[0] = { kh, kl, nullptr, gs, nullptr, nullptr };
        gemm_bf3<<<dim3(16, 16, NHEAD), gblk, GEMM_SMEM_BYTES>>>(
            qh, ql, HDTOT, HDIM, gsz, 1, HDTOT, HDIM,
            S, (long long)S * S, HDIM, scale, 0);
    }

    // combined ring softmax -> bf16 hi/lo weights (vectorized)
    ring_softmax<<<dim3(S, NHEAD), dim3(256)>>>(gs, wh, wl);

    // attn[h] = W_h @ V_h -> split bf16
    {
        GemmSets gsz = {};
        gsz.s[0] = { vth, vtl, nullptr, nullptr, ath, atl };
        gemm_bf3<<<dim3(1, 16, NHEAD), gblk, GEMM_SMEM_BYTES>>>(
            wh, wl, S, (long long)S * S, gsz, 1, S, (long long)HDIM * S,
            HDTOT, HDIM, S, 1.0f, 1);
    }

    // output projection (fp32 to d_out)
    {
        GemmSets gsz = {};
        gsz.s[0] = { owh, owl, ob, out, nullptr, nullptr };
        gemm_bf3<<<dim3(16, 16, 1), gblk, GEMM_SMEM_BYTES>>>(
            ath, atl, HDTOT, 0, gsz, 1, HDTOT, 0, HID, 0, HDTOT, 1.0f, 0);
    }
}